// round 2
// baseline (speedup 1.0000x reference)
#include <cuda_runtime.h>
#include <cuda_fp16.h>

#define B_    1024
#define T_    512
#define OBS_  64
#define H_    256
#define A_    16
#define R_    8
#define NBLK  (B_ / R_)      // 128 blocks, one wave on 148 SMs
#define NTH   256
#define ALPHA_ 0.1f

// shared memory byte offsets (all 16B aligned)
#define OFF_WH    0                      // [128][256] half2-as-u32  (k-pair major)  131072 B
#define OFF_WIN   131072                 // [32][256]  half2-as-u32                   32768 B
#define OFF_WOUT  163840                 // [16][260]  float (padded rows)            16640 B
#define OFF_HKR   180480                 // [256][8]   float  h, k-major              8192 B
#define OFF_HRK   188672                 // [8][256]   float  h, row-major            8192 B
#define OFF_OBS   196864                 // [2][64][8] float  obs double buffer       4096 B
#define SMEM_TOTAL 200960

__device__ __forceinline__ unsigned long long pack2(float x, float y) {
    unsigned long long r;
    asm("mov.b64 %0, {%1, %2};" : "=l"(r) : "f"(x), "f"(y));
    return r;
}
__device__ __forceinline__ void unpack2(unsigned long long p, float &x, float &y) {
    asm("mov.b64 {%0, %1}, %2;" : "=f"(x), "=f"(y) : "l"(p));
}
// packed fp32x2 FMA (Blackwell): d = a*b + c elementwise on (lo,hi)
__device__ __forceinline__ unsigned long long fma2(unsigned long long a,
                                                   unsigned long long b,
                                                   unsigned long long c) {
    unsigned long long d;
    asm("fma.rn.f32x2 %0, %1, %2, %3;" : "=l"(d) : "l"(a), "l"(b), "l"(c));
    return d;
}
__device__ __forceinline__ float sigmoidf_(float x) {
    return __fdividef(1.0f, 1.0f + __expf(-x));
}

__global__ void __launch_bounds__(NTH, 1)
rnn_policy_kernel(const float* __restrict__ obs,
                  const float* __restrict__ W_in,
                  const float* __restrict__ W_h,
                  const float* __restrict__ b_h,
                  const float* __restrict__ W_out,
                  const float* __restrict__ b_out,
                  float* __restrict__ out)
{
    extern __shared__ unsigned char smem[];
    unsigned int* WhS  = (unsigned int*)(smem + OFF_WH);
    unsigned int* WinS = (unsigned int*)(smem + OFF_WIN);
    float*        WoS  = (float*)(smem + OFF_WOUT);
    float*        hkr  = (float*)(smem + OFF_HKR);
    float*        hrk  = (float*)(smem + OFF_HRK);
    float*        obsS = (float*)(smem + OFF_OBS);

    const int j    = threadIdx.x;
    const int row0 = blockIdx.x * R_;

    // ---- stage weights into SMEM (one time; fp32 -> fp16 for W_h / W_in) ----
    {
        const float4* Wh4 = (const float4*)W_h;       // 16384 float4
        #pragma unroll
        for (int m = 0; m < 64; m++) {
            int idx4 = m * NTH + j;
            float4 v = Wh4[idx4];
            int jj = idx4 >> 6;            // output unit (row of W_h)
            int c4 = idx4 & 63;            // k-quad
            __half2 h01 = __floats2half2_rn(v.x, v.y);
            __half2 h23 = __floats2half2_rn(v.z, v.w);
            WhS[(c4 * 2 + 0) * H_ + jj] = *(unsigned int*)&h01;
            WhS[(c4 * 2 + 1) * H_ + jj] = *(unsigned int*)&h23;
        }
        const float4* Wi4 = (const float4*)W_in;      // 4096 float4
        #pragma unroll
        for (int m = 0; m < 16; m++) {
            int idx4 = m * NTH + j;
            float4 v = Wi4[idx4];
            int jj = idx4 >> 4;
            int c4 = idx4 & 15;
            __half2 h01 = __floats2half2_rn(v.x, v.y);
            __half2 h23 = __floats2half2_rn(v.z, v.w);
            WinS[(c4 * 2 + 0) * H_ + jj] = *(unsigned int*)&h01;
            WinS[(c4 * 2 + 1) * H_ + jj] = *(unsigned int*)&h23;
        }
        const float4* Wo4 = (const float4*)W_out;     // 1024 float4
        #pragma unroll
        for (int m = 0; m < 4; m++) {
            int idx4 = m * NTH + j;
            float4 v = Wo4[idx4];
            int a  = idx4 >> 6;
            int k4 = idx4 & 63;
            *(float4*)&WoS[a * 260 + k4 * 4] = v;     // padded rows: 2-way max conflict on read
        }
    }
    const float bh = b_h[j];
    const float bo = (j < 128) ? b_out[j & 15] : 0.0f;

    // ---- init state ----
    float hreg[R_];
    #pragma unroll
    for (int r = 0; r < R_; r++) hreg[r] = 0.0f;
    *(float4*)&hkr[j * 8]     = make_float4(0.f, 0.f, 0.f, 0.f);
    *(float4*)&hkr[j * 8 + 4] = make_float4(0.f, 0.f, 0.f, 0.f);
    #pragma unroll
    for (int r = 0; r < R_; r++) hrk[r * H_ + j] = 0.0f;
    float oreg = 0.0f;

    // obs element owned by this thread: (k, r) and (k, r+4)
    const int pk = j & 63;
    const int pr = j >> 6;

    // prefetch obs for t = 0
    {
        float v0 = obs[((long long)(row0 + pr)     * T_ + 0) * OBS_ + pk];
        float v1 = obs[((long long)(row0 + pr + 4) * T_ + 0) * OBS_ + pk];
        obsS[pk * 8 + pr]     = v0;
        obsS[pk * 8 + pr + 4] = v1;
    }
    __syncthreads();

    for (int t = 0; t < T_; t++) {
        // prefetch obs(t+1) into registers (latency hidden under phase 1)
        float p0 = 0.f, p1 = 0.f;
        if (t + 1 < T_) {
            p0 = obs[((long long)(row0 + pr)     * T_ + (t + 1)) * OBS_ + pk];
            p1 = obs[((long long)(row0 + pr + 4) * T_ + (t + 1)) * OBS_ + pk];
        }

        // ---- phase 1: pre_h[j, r] = b_h[j] + W_in[j,:]@obs + W_h[j,:]@h ----
        const float* ob = obsS + (t & 1) * (OBS_ * 8);
        unsigned long long acc01 = pack2(bh, bh);
        unsigned long long acc23 = acc01, acc45 = acc01, acc67 = acc01;

        #pragma unroll 4
        for (int kp = 0; kp < 32; kp++) {             // obs contribution, k = 2kp, 2kp+1
            unsigned int w2 = WinS[kp * H_ + j];
            float2 wf = __half22float2(*(__half2*)&w2);
            unsigned long long bx = pack2(wf.x, wf.x);
            unsigned long long by = pack2(wf.y, wf.y);
            const ulonglong2* hp = (const ulonglong2*)&ob[kp * 16];
            ulonglong2 q0 = hp[0], q1 = hp[1], q2 = hp[2], q3 = hp[3];
            acc01 = fma2(q0.x, bx, acc01); acc23 = fma2(q0.y, bx, acc23);
            acc45 = fma2(q1.x, bx, acc45); acc67 = fma2(q1.y, bx, acc67);
            acc01 = fma2(q2.x, by, acc01); acc23 = fma2(q2.y, by, acc23);
            acc45 = fma2(q3.x, by, acc45); acc67 = fma2(q3.y, by, acc67);
        }
        #pragma unroll 4
        for (int kp = 0; kp < 128; kp++) {            // recurrent contribution
            unsigned int w2 = WhS[kp * H_ + j];
            float2 wf = __half22float2(*(__half2*)&w2);
            unsigned long long bx = pack2(wf.x, wf.x);
            unsigned long long by = pack2(wf.y, wf.y);
            const ulonglong2* hp = (const ulonglong2*)&hkr[kp * 16];
            ulonglong2 q0 = hp[0], q1 = hp[1], q2 = hp[2], q3 = hp[3];
            acc01 = fma2(q0.x, bx, acc01); acc23 = fma2(q0.y, bx, acc23);
            acc45 = fma2(q1.x, bx, acc45); acc67 = fma2(q1.y, bx, acc67);
            acc01 = fma2(q2.x, by, acc01); acc23 = fma2(q2.y, by, acc23);
            acc45 = fma2(q3.x, by, acc45); acc67 = fma2(q3.y, by, acc67);
        }

        float pre[R_];
        unpack2(acc01, pre[0], pre[1]); unpack2(acc23, pre[2], pre[3]);
        unpack2(acc45, pre[4], pre[5]); unpack2(acc67, pre[6], pre[7]);
        #pragma unroll
        for (int r = 0; r < R_; r++)
            hreg[r] = (1.0f - ALPHA_) * hreg[r] + ALPHA_ * sigmoidf_(pre[r]);

        __syncthreads();   // all reads of old h / obs buffer complete

        *(float4*)&hkr[j * 8]     = make_float4(hreg[0], hreg[1], hreg[2], hreg[3]);
        *(float4*)&hkr[j * 8 + 4] = make_float4(hreg[4], hreg[5], hreg[6], hreg[7]);
        #pragma unroll
        for (int r = 0; r < R_; r++) hrk[r * H_ + j] = hreg[r];
        {
            float* obn = obsS + ((t + 1) & 1) * (OBS_ * 8);
            obn[pk * 8 + pr]     = p0;
            obn[pk * 8 + pr + 4] = p1;
        }

        __syncthreads();   // new h / obs visible

        // ---- phase 2: o update + output store (threads 0..127) ----
        if (j < 128) {
            const int a = j & 15, r = j >> 4;
            float acc = bo;
            const float4* hv4 = (const float4*)&hrk[r * H_];
            const float4* wv4 = (const float4*)&WoS[a * 260];
            #pragma unroll 8
            for (int k4 = 0; k4 < 64; k4++) {
                float4 hv = hv4[k4];
                float4 wv = wv4[k4];
                acc = fmaf(hv.x, wv.x, acc); acc = fmaf(hv.y, wv.y, acc);
                acc = fmaf(hv.z, wv.z, acc); acc = fmaf(hv.w, wv.w, acc);
            }
            oreg = (1.0f - ALPHA_) * oreg + ALPHA_ * sigmoidf_(acc);
            out[((long long)(row0 + r) * T_ + t) * A_ + a] = oreg;
        }
    }

    // ---- final states: out layout = [B,T,A] ++ [1,B,H] ++ [1,B,A] ----
    float* out_h = out + (long long)B_ * T_ * A_;
    float* out_o = out_h + (long long)B_ * H_;
    #pragma unroll
    for (int r = 0; r < R_; r++)
        out_h[(long long)(row0 + r) * H_ + j] = hreg[r];
    if (j < 128) {
        const int a = j & 15, r = j >> 4;
        out_o[(long long)(row0 + r) * A_ + a] = oreg;
    }
}

extern "C" void kernel_launch(void* const* d_in, const int* in_sizes, int n_in,
                              void* d_out, int out_size)
{
    (void)in_sizes; (void)n_in; (void)out_size;
    cudaFuncSetAttribute(rnn_policy_kernel,
                         cudaFuncAttributeMaxDynamicSharedMemorySize, SMEM_TOTAL);
    rnn_policy_kernel<<<NBLK, NTH, SMEM_TOTAL>>>(
        (const float*)d_in[0],   // obs
        (const float*)d_in[1],   // W_in
        (const float*)d_in[2],   // W_h
        (const float*)d_in[3],   // b_h
        (const float*)d_in[4],   // W_out
        (const float*)d_in[5],   // b_out
        (float*)d_out);
}

// round 5
// speedup vs baseline: 3.8782x; 3.8782x over previous
#include <cuda_runtime.h>
#include <cuda_fp16.h>
#include <cstdint>

#define B_    1024
#define T_    512
#define OBS_  64
#define H_    256
#define A_    16
#define NCOL  8               // batch columns per CTA
#define NBLK  (B_ / NCOL)     // 128 CTAs
#define NTH   544             // 17 warps: 16 hidden-tile warps + 1 output warp
#define NKC   20              // K = 320 = 20 chunks of 16

// sigmoid = rcp(1 + 2^(-x*log2e)) : MUFU.EX2 + MUFU.RCP (matches R2 accuracy)
__device__ __forceinline__ float sigm(float x) {
    float e, r;
    asm("ex2.approx.f32 %0, %1;" : "=f"(e) : "f"(-1.4426950408889634f * x));
    asm("rcp.approx.f32 %0, %1;" : "=f"(r) : "f"(1.0f + e));
    return r;
}
__device__ __forceinline__ uint32_t f2h2(float x, float y) {
    __half2 h = __floats2half2_rn(x, y);
    return *(uint32_t*)&h;
}
__device__ __forceinline__ void sts16(uint32_t addr, float v) {
    uint16_t u = __half_as_ushort(__float2half_rn(v));
    asm volatile("st.shared.u16 [%0], %1;" :: "r"(addr), "h"(u) : "memory");
}

// x-vector SMEM layout (u32 words): word(k,n) = ((k/16)*4 + ((k%16)%8)/2)*16 + n*2 + (k%16)/8
// -> thread (tig,gid)'s B-frag for chunk kc is ONE ld.shared.v2.b32 at base + kc*256.
__global__ void __launch_bounds__(NTH, 1)
rnn_hmma_kernel(const float* __restrict__ obs,  const float* __restrict__ W_in,
                const float* __restrict__ W_h,  const float* __restrict__ b_h,
                const float* __restrict__ W_out,const float* __restrict__ b_out,
                float* __restrict__ out)
{
    __shared__ __align__(16) uint32_t xS[1280];   // [h(256) | obs(64)] x 8 cols, fp16

    const int tid  = threadIdx.x;
    const int wid  = tid >> 5;
    const int gid  = (tid & 31) >> 2;   // lane group 0..7
    const int tig  = tid & 3;           // thread-in-group
    const int row0 = blockIdx.x * NCOL;
    const uint32_t xbase = (uint32_t)__cvta_generic_to_shared(xS);

    // ---------------- A fragments: weights resident in registers ----------------
    uint32_t af[NKC][4];
    const int kq = tig * 2;
    if (wid < 16) {
        const int r0 = wid * 16 + gid, r1 = r0 + 8;      // hidden units
        #pragma unroll
        for (int kc = 0; kc < 16; kc++) {
            const float* p0 = W_h + r0 * H_ + kc * 16 + kq;
            const float* p1 = W_h + r1 * H_ + kc * 16 + kq;
            float2 a = *(const float2*)(p0);     float2 b = *(const float2*)(p1);
            float2 c = *(const float2*)(p0 + 8); float2 d = *(const float2*)(p1 + 8);
            af[kc][0] = f2h2(a.x, a.y); af[kc][1] = f2h2(b.x, b.y);
            af[kc][2] = f2h2(c.x, c.y); af[kc][3] = f2h2(d.x, d.y);
        }
        #pragma unroll
        for (int kc = 16; kc < 20; kc++) {
            const float* p0 = W_in + r0 * OBS_ + (kc - 16) * 16 + kq;
            const float* p1 = W_in + r1 * OBS_ + (kc - 16) * 16 + kq;
            float2 a = *(const float2*)(p0);     float2 b = *(const float2*)(p1);
            float2 c = *(const float2*)(p0 + 8); float2 d = *(const float2*)(p1 + 8);
            af[kc][0] = f2h2(a.x, a.y); af[kc][1] = f2h2(b.x, b.y);
            af[kc][2] = f2h2(c.x, c.y); af[kc][3] = f2h2(d.x, d.y);
        }
    } else {
        const int r0 = gid, r1 = gid + 8;                // action rows
        #pragma unroll
        for (int kc = 0; kc < 16; kc++) {
            const float* p0 = W_out + r0 * H_ + kc * 16 + kq;
            const float* p1 = W_out + r1 * H_ + kc * 16 + kq;
            float2 a = *(const float2*)(p0);     float2 b = *(const float2*)(p1);
            float2 c = *(const float2*)(p0 + 8); float2 d = *(const float2*)(p1 + 8);
            af[kc][0] = f2h2(a.x, a.y); af[kc][1] = f2h2(b.x, b.y);
            af[kc][2] = f2h2(c.x, c.y); af[kc][3] = f2h2(d.x, d.y);
        }
        #pragma unroll
        for (int kc = 16; kc < 20; kc++) {               // zero frag: no-op in MMA
            af[kc][0] = 0u; af[kc][1] = 0u; af[kc][2] = 0u; af[kc][3] = 0u;
        }
    }

    float bias0, bias1;
    if (wid < 16) { bias0 = b_h[wid * 16 + gid]; bias1 = b_h[wid * 16 + gid + 8]; }
    else          { bias0 = b_out[gid];          bias1 = b_out[gid + 8]; }

    // B-fragment load address (one LDS.64 per chunk, conflict-free)
    const uint32_t baddr = xbase + (uint32_t)((tig * 8 + gid) * 8);
    // h write-back offsets (warps 0..15): 4 halfword slots
    const uint32_t hb = xbase + (uint32_t)((wid * 4 + (gid >> 1)) * 64 + tig * 16 + (gid & 1) * 2);

    // obs staging identity: one element per thread (tid < 512)
    int n_o = tid >> 6, kk = tid & 63;
    const int rem = kk & 15;
    const uint32_t ob_addr = xbase + (uint32_t)((16 + (kk >> 4)) * 256 +
                         (((rem & 7) >> 1) * 8 + n_o) * 8 + (rem >> 3) * 4 + (rem & 1) * 2);
    const float* obs_p = obs + (size_t)(row0 + n_o) * T_ * OBS_ + kk;

    // ---------------- init: zero h region, stage obs(0) ----------------
    for (int i = tid; i < 1024; i += NTH) xS[i] = 0u;
    if (tid < 512) sts16(ob_addr, obs_p[0]);

    float s0 = 0.f, s1 = 0.f, s2 = 0.f, s3 = 0.f;  // h frag (wid<16) / o frag (wid 16)
    __syncthreads();

    // ---------------- recurrence ----------------
    for (int t = 0; t < T_; t++) {
        float p = 0.0f;
        if (tid < 512 && t + 1 < T_) p = obs_p[(size_t)(t + 1) * OBS_];

        float d0 = bias0, d1 = bias0, d2 = bias1, d3 = bias1;
        #pragma unroll
        for (int kc = 0; kc < NKC; kc++) {
            uint32_t b0, b1;
            asm volatile("ld.shared.v2.b32 {%0,%1}, [%2];"
                         : "=r"(b0), "=r"(b1) : "r"(baddr + kc * 256));
            asm("mma.sync.aligned.m16n8k16.row.col.f32.f16.f16.f32 "
                "{%0,%1,%2,%3}, {%4,%5,%6,%7}, {%8,%9}, {%0,%1,%2,%3};"
                : "+f"(d0), "+f"(d1), "+f"(d2), "+f"(d3)
                : "r"(af[kc][0]), "r"(af[kc][1]), "r"(af[kc][2]), "r"(af[kc][3]),
                  "r"(b0), "r"(b1));
        }

        if (wid < 16) {
            s0 = 0.9f * s0 + 0.1f * sigm(d0);
            s1 = 0.9f * s1 + 0.1f * sigm(d1);
            s2 = 0.9f * s2 + 0.1f * sigm(d2);
            s3 = 0.9f * s3 + 0.1f * sigm(d3);
        } else if (t > 0) {                    // consumes h_{t-1} -> emits out[t-1]
            s0 = 0.9f * s0 + 0.1f * sigm(d0);
            s1 = 0.9f * s1 + 0.1f * sigm(d1);
            s2 = 0.9f * s2 + 0.1f * sigm(d2);
            s3 = 0.9f * s3 + 0.1f * sigm(d3);
            const int c0 = tig * 2;
            size_t o0i = ((size_t)(row0 + c0)     * T_ + (t - 1)) * A_ + gid;
            size_t o1i = ((size_t)(row0 + c0 + 1) * T_ + (t - 1)) * A_ + gid;
            out[o0i] = s0; out[o1i] = s1; out[o0i + 8] = s2; out[o1i + 8] = s3;
        }

        __syncthreads();   // all B-frag reads of xS complete

        if (wid < 16) {    // write h_t back as fp16 B-operand
            sts16(hb,      s0);
            sts16(hb + 8,  s1);
            sts16(hb + 4,  s2);
            sts16(hb + 12, s3);
        }
        if (tid < 512) sts16(ob_addr, p);      // obs(t+1)

        __syncthreads();   // x ready for step t+1
    }

    // ---------------- epilogue ----------------
    float* out_h = out + (size_t)B_ * T_ * A_;
    float* out_o = out_h + (size_t)B_ * H_;

    if (wid < 16) {
        const int r0 = wid * 16 + gid, r1 = r0 + 8, c0 = tig * 2;
        out_h[(size_t)(row0 + c0)     * H_ + r0] = s0;
        out_h[(size_t)(row0 + c0 + 1) * H_ + r0] = s1;
        out_h[(size_t)(row0 + c0)     * H_ + r1] = s2;
        out_h[(size_t)(row0 + c0 + 1) * H_ + r1] = s3;
    } else {
        // final o-update consuming h_{T-1}
        float d0 = bias0, d1 = bias0, d2 = bias1, d3 = bias1;
        #pragma unroll
        for (int kc = 0; kc < NKC; kc++) {
            uint32_t b0, b1;
            asm volatile("ld.shared.v2.b32 {%0,%1}, [%2];"
                         : "=r"(b0), "=r"(b1) : "r"(baddr + kc * 256));
            asm("mma.sync.aligned.m16n8k16.row.col.f32.f16.f16.f32 "
                "{%0,%1,%2,%3}, {%4,%5,%6,%7}, {%8,%9}, {%0,%1,%2,%3};"
                : "+f"(d0), "+f"(d1), "+f"(d2), "+f"(d3)
                : "r"(af[kc][0]), "r"(af[kc][1]), "r"(af[kc][2]), "r"(af[kc][3]),
                  "r"(b0), "r"(b1));
        }
        s0 = 0.9f * s0 + 0.1f * sigm(d0);
        s1 = 0.9f * s1 + 0.1f * sigm(d1);
        s2 = 0.9f * s2 + 0.1f * sigm(d2);
        s3 = 0.9f * s3 + 0.1f * sigm(d3);
        const int c0 = tig * 2;
        size_t o0i = ((size_t)(row0 + c0)     * T_ + (T_ - 1)) * A_ + gid;
        size_t o1i = ((size_t)(row0 + c0 + 1) * T_ + (T_ - 1)) * A_ + gid;
        out[o0i] = s0; out[o1i] = s1; out[o0i + 8] = s2; out[o1i + 8] = s3;
        out_o[(size_t)(row0 + c0)     * A_ + gid]     = s0;
        out_o[(size_t)(row0 + c0 + 1) * A_ + gid]     = s1;
        out_o[(size_t)(row0 + c0)     * A_ + gid + 8] = s2;
        out_o[(size_t)(row0 + c0 + 1) * A_ + gid + 8] = s3;
    }
}

extern "C" void kernel_launch(void* const* d_in, const int* in_sizes, int n_in,
                              void* d_out, int out_size)
{
    (void)in_sizes; (void)n_in; (void)out_size;
    rnn_hmma_kernel<<<NBLK, NTH>>>(
        (const float*)d_in[0],   // obs
        (const float*)d_in[1],   // W_in
        (const float*)d_in[2],   // W_h
        (const float*)d_in[3],   // b_h
        (const float*)d_in[4],   // W_out
        (const float*)d_in[5],   // b_out
        (float*)d_out);
}

// round 7
// speedup vs baseline: 4.1061x; 1.0588x over previous
#include <cuda_runtime.h>
#include <cuda_fp16.h>
#include <cstdint>

#define B_    1024
#define T_    512
#define OBS_  64
#define H_    256
#define A_    16
#define NCOL  8               // batch columns per CTA
#define NBLK  (B_ / NCOL)     // 128 CTAs
#define NTH   288             // 8 compute warps (2 m16-tiles each) + 1 output warp
#define XBUF  5120            // bytes per x buffer ([h;obs] x 8 cols fp16)

__device__ __forceinline__ float sigm(float x) {           // accurate: EX2 + RCP
    float e, r;
    asm("ex2.approx.f32 %0, %1;" : "=f"(e) : "f"(-1.4426950408889634f * x));
    asm("rcp.approx.f32 %0, %1;" : "=f"(r) : "f"(1.0f + e));
    return r;
}
__device__ __forceinline__ float tanh_(float x) {          // fast path for h
    float t;
    asm("tanh.approx.f32 %0, %1;" : "=f"(t) : "f"(x));
    return t;
}
__device__ __forceinline__ uint32_t f2h2(float x, float y) {
    __half2 h = __floats2half2_rn(x, y);
    return *(uint32_t*)&h;
}
__device__ __forceinline__ void sts16(uint32_t a, float v) {
    uint16_t u = __half_as_ushort(__float2half_rn(v));
    asm volatile("st.shared.u16 [%0], %1;" :: "r"(a), "h"(u) : "memory");
}
__device__ __forceinline__ void ldfrag(uint32_t* f, const float* p0, const float* p1) {
    float2 a = *(const float2*)p0,       b = *(const float2*)p1;
    float2 c = *(const float2*)(p0 + 8), d = *(const float2*)(p1 + 8);
    f[0] = f2h2(a.x, a.y); f[1] = f2h2(b.x, b.y);
    f[2] = f2h2(c.x, c.y); f[3] = f2h2(d.x, d.y);
}
#define MMA(d0,d1,d2,d3,a,b0,b1) \
    asm("mma.sync.aligned.m16n8k16.row.col.f32.f16.f16.f32 " \
        "{%0,%1,%2,%3},{%4,%5,%6,%7},{%8,%9},{%0,%1,%2,%3};" \
        : "+f"(d0), "+f"(d1), "+f"(d2), "+f"(d3) \
        : "r"((a)[0]), "r"((a)[1]), "r"((a)[2]), "r"((a)[3]), "r"(b0), "r"(b1))
#define LDSV2(b0,b1,addr) \
    asm volatile("ld.shared.v2.b32 {%0,%1}, [%2];" : "=r"(b0), "=r"(b1) : "r"(addr))

// x layout per buffer (u32 words): word(k,n) = ((k>>4)*4 + ((k&7)>>1))*16 + 2n + ((k>>3)&1),
// halfword k&1.  B-frag of thread (tig,gid) for chunk kc = ONE ld.shared.v2.b32
// at xbase + (tig*8+gid)*8 + kc*256.
__global__ void __launch_bounds__(NTH, 1)
rnn_hmma2_kernel(const float* __restrict__ obs,   const float* __restrict__ W_in,
                 const float* __restrict__ W_h,   const float* __restrict__ b_h,
                 const float* __restrict__ W_out, const float* __restrict__ b_out,
                 float* __restrict__ out)
{
    __shared__ __align__(16) uint32_t xS[2 * 1280];

    const int tid  = threadIdx.x;
    const int wid  = tid >> 5;
    const int gid  = (tid & 31) >> 2;
    const int tig  = tid & 3;
    const int kq   = tig * 2;
    const int row0 = blockIdx.x * NCOL;
    const uint32_t xbase = (uint32_t)__cvta_generic_to_shared(xS);
    const uint32_t baddr = xbase + (uint32_t)((tig * 8 + gid) * 8);

    float* out_h = out + (size_t)B_ * T_ * A_;
    float* out_o = out_h + (size_t)B_ * H_;

    // ---- init: zero both x buffers, stage obs(0) ----
    for (int i = tid; i < 2560; i += NTH) xS[i] = 0u;
    __syncthreads();

    // obs staging identity (threads 0..255: rows n_ob and n_ob+4, element kk)
    const int n_ob = tid >> 6, kk = tid & 63;
    const uint32_t obA = xbase + (uint32_t)((16 + (kk >> 4)) * 256 + ((kk & 7) >> 1) * 64 +
                                            n_ob * 8 + ((kk >> 3) & 1) * 4 + (kk & 1) * 2);
    const float* op = obs + (size_t)(row0 + n_ob) * T_ * OBS_ + kk;
    const size_t OSTR = (size_t)4 * T_ * OBS_;          // +4 batch rows
    if (tid < 256) { sts16(obA, op[0]); sts16(obA + 32, op[OSTR]); }

    if (wid < 8) {
        // ================= compute warps: 2 m16-tiles of pre_h =================
        const int rbase = wid * 32;
        uint32_t af[2][20][4];
        #pragma unroll
        for (int m = 0; m < 2; m++) {
            const int rA = rbase + m * 16 + gid;
            #pragma unroll
            for (int kc = 0; kc < 16; kc++)
                ldfrag(af[m][kc], W_h + rA * H_ + kc * 16 + kq,
                                  W_h + (rA + 8) * H_ + kc * 16 + kq);
            #pragma unroll
            for (int kc = 16; kc < 20; kc++)
                ldfrag(af[m][kc], W_in + rA * OBS_ + (kc - 16) * 16 + kq,
                                  W_in + (rA + 8) * OBS_ + (kc - 16) * 16 + kq);
        }
        const float bh0 = b_h[rbase + gid],      bh1 = b_h[rbase + gid + 8];
        const float bh2 = b_h[rbase + gid + 16], bh3 = b_h[rbase + gid + 24];

        // h write-back base: row rbase+gid, col 2*tig; offsets {0,8,4,12,256,264,260,268}
        const uint32_t hA = xbase +
            (uint32_t)(4 * (((((rbase >> 4) << 2) | (gid >> 1)) << 4) + 4 * tig) + (gid & 1) * 2);

        float s00 = 0.f, s01 = 0.f, s02 = 0.f, s03 = 0.f;
        float s10 = 0.f, s11 = 0.f, s12 = 0.f, s13 = 0.f;

        for (int t = 0; t < T_; t++) {
            __syncthreads();                               // x[t&1] ready
            float p0 = 0.f, p1 = 0.f;
            if (tid < 256 && t + 1 < T_) {
                p0 = op[(size_t)(t + 1) * OBS_];
                p1 = op[(size_t)(t + 1) * OBS_ + OSTR];
            }
            const uint32_t xb = baddr + (uint32_t)((t & 1) * XBUF);

            float A0 = bh0, A1 = bh0, A2 = bh1, A3 = bh1;  // tile0 even chunks
            float Bb0 = 0.f, Bb1 = 0.f, Bb2 = 0.f, Bb3 = 0.f; // tile0 odd
            float C0 = bh2, C1 = bh2, C2 = bh3, C3 = bh3;  // tile1 even
            float D0 = 0.f, D1 = 0.f, D2 = 0.f, D3 = 0.f;  // tile1 odd
            #pragma unroll
            for (int kc = 0; kc < 20; kc += 2) {
                uint32_t b0, b1, c0, c1;
                LDSV2(b0, b1, xb + kc * 256);
                LDSV2(c0, c1, xb + (kc + 1) * 256);
                MMA(A0, A1, A2, A3, af[0][kc], b0, b1);
                MMA(C0, C1, C2, C3, af[1][kc], b0, b1);
                MMA(Bb0, Bb1, Bb2, Bb3, af[0][kc + 1], c0, c1);
                MMA(D0, D1, D2, D3, af[1][kc + 1], c0, c1);
            }
            s00 = fmaf(0.9f, s00, fmaf(0.05f, tanh_(0.5f * (A0 + Bb0)), 0.05f));
            s01 = fmaf(0.9f, s01, fmaf(0.05f, tanh_(0.5f * (A1 + Bb1)), 0.05f));
            s02 = fmaf(0.9f, s02, fmaf(0.05f, tanh_(0.5f * (A2 + Bb2)), 0.05f));
            s03 = fmaf(0.9f, s03, fmaf(0.05f, tanh_(0.5f * (A3 + Bb3)), 0.05f));
            s10 = fmaf(0.9f, s10, fmaf(0.05f, tanh_(0.5f * (C0 + D0)), 0.05f));
            s11 = fmaf(0.9f, s11, fmaf(0.05f, tanh_(0.5f * (C1 + D1)), 0.05f));
            s12 = fmaf(0.9f, s12, fmaf(0.05f, tanh_(0.5f * (C2 + D2)), 0.05f));
            s13 = fmaf(0.9f, s13, fmaf(0.05f, tanh_(0.5f * (C3 + D3)), 0.05f));

            const uint32_t hw = hA + (uint32_t)(((t + 1) & 1) * XBUF);
            sts16(hw,       s00); sts16(hw + 8,   s01);
            sts16(hw + 4,   s02); sts16(hw + 12,  s03);
            sts16(hw + 256, s10); sts16(hw + 264, s11);
            sts16(hw + 260, s12); sts16(hw + 268, s13);
            if (tid < 256) {
                const uint32_t ow = obA + (uint32_t)(((t + 1) & 1) * XBUF);
                sts16(ow, p0); sts16(ow + 32, p1);
            }
        }
        __syncthreads();

        // final h states: rows {rbase+gid,+8,+16,+24}, cols {2tig, 2tig+1}
        const int c0 = tig * 2, j0 = rbase + gid;
        out_h[(size_t)(row0 + c0)     * H_ + j0]      = s00;
        out_h[(size_t)(row0 + c0 + 1) * H_ + j0]      = s01;
        out_h[(size_t)(row0 + c0)     * H_ + j0 + 8]  = s02;
        out_h[(size_t)(row0 + c0 + 1) * H_ + j0 + 8]  = s03;
        out_h[(size_t)(row0 + c0)     * H_ + j0 + 16] = s10;
        out_h[(size_t)(row0 + c0 + 1) * H_ + j0 + 16] = s11;
        out_h[(size_t)(row0 + c0)     * H_ + j0 + 24] = s12;
        out_h[(size_t)(row0 + c0 + 1) * H_ + j0 + 24] = s13;
    } else {
        // ================= output warp: pre_o = W_out @ h (one step behind) =================
        uint32_t afo[16][4];
        #pragma unroll
        for (int kc = 0; kc < 16; kc++)
            ldfrag(afo[kc], W_out + gid * H_ + kc * 16 + kq,
                            W_out + (gid + 8) * H_ + kc * 16 + kq);
        const float bo0 = b_out[gid], bo1 = b_out[gid + 8];
        float s0 = 0.f, s1 = 0.f, s2 = 0.f, s3 = 0.f;
        const int c0 = tig * 2;

        for (int t = 0; t < T_; t++) {
            __syncthreads();
            if (t > 0) {
                const uint32_t xb = baddr + (uint32_t)((t & 1) * XBUF);
                float E0 = bo0, E1 = bo0, E2 = bo1, E3 = bo1;
                float O0 = 0.f, O1 = 0.f, O2 = 0.f, O3 = 0.f;
                #pragma unroll
                for (int kc = 0; kc < 16; kc += 2) {
                    uint32_t b0, b1, c1, c2;
                    LDSV2(b0, b1, xb + kc * 256);
                    LDSV2(c1, c2, xb + (kc + 1) * 256);
                    MMA(E0, E1, E2, E3, afo[kc], b0, b1);
                    MMA(O0, O1, O2, O3, afo[kc + 1], c1, c2);
                }
                s0 = fmaf(0.9f, s0, 0.1f * sigm(E0 + O0));
                s1 = fmaf(0.9f, s1, 0.1f * sigm(E1 + O1));
                s2 = fmaf(0.9f, s2, 0.1f * sigm(E2 + O2));
                s3 = fmaf(0.9f, s3, 0.1f * sigm(E3 + O3));
                size_t o0i = ((size_t)(row0 + c0)     * T_ + (t - 1)) * A_ + gid;
                size_t o1i = ((size_t)(row0 + c0 + 1) * T_ + (t - 1)) * A_ + gid;
                out[o0i] = s0; out[o1i] = s1; out[o0i + 8] = s2; out[o1i + 8] = s3;
            }
        }
        __syncthreads();

        // final pass: consume h_{T-1} from buf[T&1]==buf0
        {
            const uint32_t xb = baddr;
            float E0 = bo0, E1 = bo0, E2 = bo1, E3 = bo1;
            float O0 = 0.f, O1 = 0.f, O2 = 0.f, O3 = 0.f;
            #pragma unroll
            for (int kc = 0; kc < 16; kc += 2) {
                uint32_t b0, b1, c1, c2;
                LDSV2(b0, b1, xb + kc * 256);
                LDSV2(c1, c2, xb + (kc + 1) * 256);
                MMA(E0, E1, E2, E3, afo[kc], b0, b1);
                MMA(O0, O1, O2, O3, afo[kc + 1], c1, c2);
            }
            s0 = fmaf(0.9f, s0, 0.1f * sigm(E0 + O0));
            s1 = fmaf(0.9f, s1, 0.1f * sigm(E1 + O1));
            s2 = fmaf(0.9f, s2, 0.1f * sigm(E2 + O2));
            s3 = fmaf(0.9f, s3, 0.1f * sigm(E3 + O3));
            size_t o0i = ((size_t)(row0 + c0)     * T_ + (T_ - 1)) * A_ + gid;
            size_t o1i = ((size_t)(row0 + c0 + 1) * T_ + (T_ - 1)) * A_ + gid;
            out[o0i] = s0; out[o1i] = s1; out[o0i + 8] = s2; out[o1i + 8] = s3;
            out_o[(size_t)(row0 + c0)     * A_ + gid]     = s0;
            out_o[(size_t)(row0 + c0 + 1) * A_ + gid]     = s1;
            out_o[(size_t)(row0 + c0)     * A_ + gid + 8] = s2;
            out_o[(size_t)(row0 + c0 + 1) * A_ + gid + 8] = s3;
        }
    }
}

extern "C" void kernel_launch(void* const* d_in, const int* in_sizes, int n_in,
                              void* d_out, int out_size)
{
    (void)in_sizes; (void)n_in; (void)out_size;
    rnn_hmma2_kernel<<<NBLK, NTH>>>(
        (const float*)d_in[0],   // obs
        (const float*)d_in[1],   // W_in
        (const float*)d_in[2],   // W_h
        (const float*)d_in[3],   // b_h
        (const float*)d_in[4],   // W_out
        (const float*)d_in[5],   // b_out
        (float*)d_out);
}